// round 3
// baseline (speedup 1.0000x reference)
#include <cuda_runtime.h>
#include <math.h>

#define BQ 8
#define NCH 128
#define NPOS 4096
#define INPC 256
#define UPC 1024
#define MDC 128
#define ICC 512
#define DINC 256
#define LSEQ 4096
#define NSEQ 32
#define EPSV 1e-5f

__device__ __align__(16) float g_x1 [(size_t)BQ*ICC*NPOS];
__device__ __align__(16) float g_x2 [(size_t)BQ*ICC*NPOS];
__device__ __align__(16) float g_s0 [BQ*UPC];
__device__ __align__(16) float g_s  [BQ*UPC];
__device__ __align__(16) float g_Fp [(size_t)BQ*MDC*NPOS];
__device__ __align__(16) float g_X4 [(size_t)NSEQ*LSEQ*MDC];
__device__ __align__(16) float g_xz [(size_t)NSEQ*LSEQ*2*DINC];
__device__ __align__(16) float g_u  [(size_t)NSEQ*LSEQ*DINC];
__device__ __align__(16) float g_dbl[(size_t)NSEQ*LSEQ*10];
__device__ __align__(16) float g_dt [(size_t)NSEQ*LSEQ*DINC];
__device__ __align__(16) float g_Bv [NSEQ*LSEQ];
__device__ __align__(16) float g_Cv [NSEQ*LSEQ];
__device__ __align__(16) float g_yf [(size_t)NSEQ*LSEQ*DINC];
__device__ __align__(16) float g_Y4 [(size_t)NSEQ*LSEQ*MDC];
__device__ __align__(16) float g_ysum[(size_t)BQ*LSEQ*MDC];

__device__ __forceinline__ float sigf(float x){ return 1.f/(1.f+expf(-x)); }

__device__ __forceinline__ void mm_tile(const float (&As)[8][128], const float (&Bs)[8][128],
                                        float (&acc)[8][8], int tr, int tc)
{
#pragma unroll
  for (int k = 0; k < 8; ++k) {
    float4 a0 = *(const float4*)&As[k][tr*8];
    float4 a1 = *(const float4*)&As[k][tr*8+4];
    float4 b0 = *(const float4*)&Bs[k][tc*8];
    float4 b1 = *(const float4*)&Bs[k][tc*8+4];
    float av[8] = {a0.x,a0.y,a0.z,a0.w,a1.x,a1.y,a1.z,a1.w};
    float bw[8] = {b0.x,b0.y,b0.z,b0.w,b1.x,b1.y,b1.z,b1.w};
#pragma unroll
    for (int i=0;i<8;i++)
#pragma unroll
      for (int j=0;j<8;j++)
        acc[i][j] = fmaf(av[i], bw[j], acc[i][j]);
  }
}

// K1: conv1x1 (256->512) + BN1 + ReLU
__global__ __launch_bounds__(256) void k1_conv1(
    const float* __restrict__ FT1, const float* __restrict__ FT2,
    const float* __restrict__ W,  const float* __restrict__ g1,
    const float* __restrict__ b1, const float* __restrict__ m1,
    const float* __restrict__ v1)
{
  __shared__ __align__(16) float As[8][128];
  __shared__ __align__(16) float Bs[8][128];
  const int b=blockIdx.z, m0=blockIdx.y*128, n0=blockIdx.x*128, tid=threadIdx.x;
  const int tr=tid>>4, tc=tid&15, am=tid>>1, ak=(tid&1)*4;
  const int bn=(tid&31)*4, bk=tid>>5;
  float acc[8][8]={};
  const float* f1 = FT1 + (size_t)b*NCH*NPOS;
  const float* f2 = FT2 + (size_t)b*NCH*NPOS;
  for (int k0=0;k0<INPC;k0+=8){
    float4 av = *(const float4*)&W[(size_t)(m0+am)*INPC + k0+ak];
    const int ci = k0 + bk;
    const float* src = (ci<NCH) ? (f1 + (size_t)ci*NPOS) : (f2 + (size_t)(ci-NCH)*NPOS);
    float4 bv4 = *(const float4*)&src[n0+bn];
    As[ak+0][am]=av.x; As[ak+1][am]=av.y; As[ak+2][am]=av.z; As[ak+3][am]=av.w;
    *(float4*)&Bs[bk][bn] = bv4;
    __syncthreads();
    mm_tile(As,Bs,acc,tr,tc);
    __syncthreads();
  }
#pragma unroll
  for (int i=0;i<8;i++){
    const int co = m0 + tr*8 + i;
    const float sc = g1[co]*rsqrtf(v1[co]+EPSV);
    const float bi = b1[co] - m1[co]*sc;
    float* orow = g_x1 + ((size_t)b*ICC + co)*NPOS + n0 + tc*8;
    float4 o0,o1;
    o0.x=fmaxf(fmaf(acc[i][0],sc,bi),0.f); o0.y=fmaxf(fmaf(acc[i][1],sc,bi),0.f);
    o0.z=fmaxf(fmaf(acc[i][2],sc,bi),0.f); o0.w=fmaxf(fmaf(acc[i][3],sc,bi),0.f);
    o1.x=fmaxf(fmaf(acc[i][4],sc,bi),0.f); o1.y=fmaxf(fmaf(acc[i][5],sc,bi),0.f);
    o1.z=fmaxf(fmaf(acc[i][6],sc,bi),0.f); o1.w=fmaxf(fmaf(acc[i][7],sc,bi),0.f);
    *(float4*)&orow[0]=o0; *(float4*)&orow[4]=o1;
  }
}

// K2: depthwise 3x3 + BN2 + ReLU
__global__ __launch_bounds__(256) void k2_dw(
    const float* __restrict__ W3, const float* __restrict__ g2,
    const float* __restrict__ b2, const float* __restrict__ m2,
    const float* __restrict__ v2)
{
  const int bc = blockIdx.x;
  const int c = bc & (ICC-1);
  const float* plane = g_x1 + (size_t)bc*NPOS;
  float w[9];
#pragma unroll
  for (int i=0;i<9;i++) w[i]=W3[c*9+i];
  const float sc = g2[c]*rsqrtf(v2[c]+EPSV);
  const float bi = b2[c]-m2[c]*sc;
  float* outp = g_x2 + (size_t)bc*NPOS;
  for (int p = threadIdx.x; p < NPOS; p += 256){
    const int h=p>>6, ww=p&63;
    float a=0.f;
#pragma unroll
    for (int di=-1;di<=1;di++){
      const int hh=h+di;
      if ((unsigned)hh < 64u){
#pragma unroll
        for (int dj=-1;dj<=1;dj++){
          const int wq=ww+dj;
          if ((unsigned)wq < 64u)
            a = fmaf(w[(di+1)*3+dj+1], plane[hh*64+wq], a);
        }
      }
    }
    outp[p] = fmaxf(fmaf(a,sc,bi),0.f);
  }
}

// SE mean over H*W
__global__ __launch_bounds__(256) void k_se_reduce()
{
  __shared__ float red[256];
  const int bc = blockIdx.x;
  const int b = bc >> 10, c = bc & 1023;
  const float* plane = (c < ICC) ? (g_x1 + ((size_t)b*ICC + c)*NPOS)
                                 : (g_x2 + ((size_t)b*ICC + (c-ICC))*NPOS);
  float s=0.f;
  for (int p=threadIdx.x;p<NPOS;p+=256) s += plane[p];
  red[threadIdx.x]=s; __syncthreads();
  for (int o=128;o>0;o>>=1){ if(threadIdx.x<o) red[threadIdx.x]+=red[threadIdx.x+o]; __syncthreads(); }
  if (threadIdx.x==0) g_s0[b*UPC+c] = red[0] * (1.f/NPOS);
}

// SE MLP
__global__ __launch_bounds__(256) void k_se_mlp(const float* __restrict__ w1, const float* __restrict__ w2)
{
  __shared__ float s0[1024];
  __shared__ float part[256];
  __shared__ float hid[64];
  const int b = blockIdx.x, tid = threadIdx.x;
  for (int c=tid;c<1024;c+=256) s0[c]=g_s0[b*UPC+c];
  __syncthreads();
  const int j = tid>>2, q = tid&3;
  float p=0.f;
  for (int c=q*256;c<q*256+256;c++) p = fmaf(s0[c], w1[j*1024+c], p);
  part[tid]=p; __syncthreads();
  if (tid<64){
    float h = part[tid*4]+part[tid*4+1]+part[tid*4+2]+part[tid*4+3];
    hid[tid]=fmaxf(h,0.f);
  }
  __syncthreads();
  for (int c=tid;c<1024;c+=256){
    float a=0.f;
#pragma unroll
    for (int jj=0;jj<64;jj++) a = fmaf(hid[jj], w2[c*64+jj], a);
    g_s[b*UPC+c] = sigf(a);
  }
}

// K4: proj conv1x1 (1024->128) with SE scale fused + BN3
__global__ __launch_bounds__(256) void k4_proj(
    const float* __restrict__ PW, const float* __restrict__ g3,
    const float* __restrict__ b3, const float* __restrict__ m3,
    const float* __restrict__ v3)
{
  __shared__ __align__(16) float As[8][128];
  __shared__ __align__(16) float Bs[8][128];
  const int b=blockIdx.z, n0=blockIdx.x*128, tid=threadIdx.x;
  const int tr=tid>>4, tc=tid&15, am=tid>>1, ak=(tid&1)*4;
  const int bn=(tid&31)*4, bk=tid>>5;
  float acc[8][8]={};
  for (int k0=0;k0<UPC;k0+=8){
    float4 av = *(const float4*)&PW[(size_t)am*UPC + k0+ak];
    const int c = k0 + bk;
    const float* src = (c<ICC) ? (g_x1 + ((size_t)b*ICC + c)*NPOS)
                               : (g_x2 + ((size_t)b*ICC + (c-ICC))*NPOS);
    const float sv = g_s[b*UPC + c];
    float4 bv4 = *(const float4*)&src[n0+bn];
    bv4.x*=sv; bv4.y*=sv; bv4.z*=sv; bv4.w*=sv;
    As[ak+0][am]=av.x; As[ak+1][am]=av.y; As[ak+2][am]=av.z; As[ak+3][am]=av.w;
    *(float4*)&Bs[bk][bn]=bv4;
    __syncthreads();
    mm_tile(As,Bs,acc,tr,tc);
    __syncthreads();
  }
#pragma unroll
  for (int i=0;i<8;i++){
    const int d = tr*8 + i;
    const float sc = g3[d]*rsqrtf(v3[d]+EPSV);
    const float bi = b3[d] - m3[d]*sc;
    float* orow = g_Fp + ((size_t)b*MDC + d)*NPOS + n0 + tc*8;
    float4 o0,o1;
    o0.x=fmaf(acc[i][0],sc,bi); o0.y=fmaf(acc[i][1],sc,bi);
    o0.z=fmaf(acc[i][2],sc,bi); o0.w=fmaf(acc[i][3],sc,bi);
    o1.x=fmaf(acc[i][4],sc,bi); o1.y=fmaf(acc[i][5],sc,bi);
    o1.z=fmaf(acc[i][6],sc,bi); o1.w=fmaf(acc[i][7],sc,bi);
    *(float4*)&orow[0]=o0; *(float4*)&orow[4]=o1;
  }
}

// K5: build X4
__global__ __launch_bounds__(256) void k5_x4()
{
  const int gid = blockIdx.x*256 + threadIdx.x;
  const int d4 = (gid & 31)*4;
  const int l  = (gid>>5) & 4095;
  const int n  = gid>>17;
  const int dir = n>>3, b = n&7;
  int p;
  if (dir==0)      p = l;
  else if (dir==1) p = (l & ~63) + 63 - (l & 63);
  else if (dir==2) p = ((l&63)<<6) + (l>>6);
  else             p = ((63-(l&63))<<6) + (l>>6);
  const float* fp = g_Fp + (size_t)b*MDC*NPOS + p;
  float4 v;
  v.x = fp[(size_t)(d4+0)*NPOS];
  v.y = fp[(size_t)(d4+1)*NPOS];
  v.z = fp[(size_t)(d4+2)*NPOS];
  v.w = fp[(size_t)(d4+3)*NPOS];
  *(float4*)&g_X4[((size_t)n*LSEQ + l)*MDC + d4] = v;
}

// K6: in_proj GEMM (131072x128 @ 512x128^T)
__global__ __launch_bounds__(256) void k6_inproj(const float* __restrict__ Wi)
{
  __shared__ __align__(16) float As[8][128];
  __shared__ __align__(16) float Bs[8][128];
  const int n0 = blockIdx.x*128;
  const size_t m0 = (size_t)blockIdx.y*128;
  const int tid=threadIdx.x, tr=tid>>4, tc=tid&15, am=tid>>1, ak=(tid&1)*4;
  float acc[8][8]={};
  for (int k0=0;k0<MDC;k0+=8){
    float4 av = *(const float4*)&g_X4[(m0+am)*MDC + k0+ak];
    float4 wv = *(const float4*)&Wi[(size_t)(n0+am)*MDC + k0+ak];
    As[ak+0][am]=av.x; As[ak+1][am]=av.y; As[ak+2][am]=av.z; As[ak+3][am]=av.w;
    Bs[ak+0][am]=wv.x; Bs[ak+1][am]=wv.y; Bs[ak+2][am]=wv.z; Bs[ak+3][am]=wv.w;
    __syncthreads();
    mm_tile(As,Bs,acc,tr,tc);
    __syncthreads();
  }
#pragma unroll
  for (int i=0;i<8;i++){
    float* orow = g_xz + (m0 + tr*8 + i)*(2*DINC) + n0 + tc*8;
    float4 o0 = {acc[i][0],acc[i][1],acc[i][2],acc[i][3]};
    float4 o1 = {acc[i][4],acc[i][5],acc[i][6],acc[i][7]};
    *(float4*)&orow[0]=o0; *(float4*)&orow[4]=o1;
  }
}

// K7: causal depthwise conv1d (k=4) + SiLU
__global__ __launch_bounds__(256) void k7_conv1d(const float* __restrict__ CW, const float* __restrict__ CB)
{
  const int gid = blockIdx.x*256+threadIdx.x;
  const int d4 = (gid & 63)*4;
  const int l  = (gid>>6) & 4095;
  const int n  = gid>>18;
  const float* base = g_xz + (size_t)n*LSEQ*(2*DINC) + d4;
  float4 acc = { CB[d4], CB[d4+1], CB[d4+2], CB[d4+3] };
  float w[4][4];
#pragma unroll
  for (int i=0;i<4;i++){
    float4 wr = *(const float4*)&CW[(d4+i)*4];
    w[i][0]=wr.x; w[i][1]=wr.y; w[i][2]=wr.z; w[i][3]=wr.w;
  }
#pragma unroll
  for (int k=0;k<4;k++){
    const int lt = l-3+k;
    if (lt>=0){
      float4 x = *(const float4*)&base[(size_t)lt*(2*DINC)];
      acc.x = fmaf(w[0][k], x.x, acc.x);
      acc.y = fmaf(w[1][k], x.y, acc.y);
      acc.z = fmaf(w[2][k], x.z, acc.z);
      acc.w = fmaf(w[3][k], x.w, acc.w);
    }
  }
  acc.x *= sigf(acc.x); acc.y *= sigf(acc.y);
  acc.z *= sigf(acc.z); acc.w *= sigf(acc.w);
  *(float4*)&g_u[((size_t)n*LSEQ + l)*DINC + d4] = acc;
}

// K8: x_proj (u @ xw^T -> 10 cols), one warp per row
__global__ __launch_bounds__(256) void k8_xproj(const float* __restrict__ XW)
{
  __shared__ float xw[10*DINC];
  const int tid = threadIdx.x;
  for (int i=tid;i<10*DINC;i+=256) xw[i]=XW[i];
  __syncthreads();
  const int warp = tid>>5, lane = tid&31;
  const size_t r = (size_t)blockIdx.x*8 + warp;
  const float* urow = g_u + r*DINC;
  float uv[8];
#pragma unroll
  for (int i=0;i<8;i++) uv[i]=urow[lane+32*i];
#pragma unroll
  for (int j=0;j<10;j++){
    float p=0.f;
#pragma unroll
    for (int i=0;i<8;i++) p = fmaf(uv[i], xw[j*DINC+lane+32*i], p);
#pragma unroll
    for (int o=16;o>0;o>>=1) p += __shfl_xor_sync(0xffffffffu, p, o);
    if (lane==0) g_dbl[r*10+j]=p;
  }
}

// K9: dt = softplus(dbl[:,:8] @ dtw^T + b); extract B,C
__global__ __launch_bounds__(256) void k9_dt(const float* __restrict__ DTW, const float* __restrict__ DTB)
{
  const int d = threadIdx.x;
  float w[8];
#pragma unroll
  for (int q=0;q<8;q++) w[q]=DTW[d*8+q];
  const float bb = DTB[d];
  const size_t r0 = (size_t)blockIdx.x*8;
  for (int rr=0;rr<8;rr++){
    const size_t r = r0+rr;
    const float* db = g_dbl + r*10;
    float pre = bb;
#pragma unroll
    for (int q=0;q<8;q++) pre = fmaf(db[q], w[q], pre);
    const float sp = (pre>20.f)? pre : log1pf(expf(pre));
    g_dt[r*DINC+d]=sp;
    if (d==0){ g_Bv[r]=db[8]; g_Cv[r]=db[9]; }
  }
}

// K10: selective scan + fused (y+u*D)*silu(z)
__global__ __launch_bounds__(256) void k10_scan(const float* __restrict__ AL, const float* __restrict__ DP)
{
  const int n = blockIdx.x, d = threadIdx.x;
  const float Ad = -expf(AL[d]);
  const float Dpd = DP[d];
  const size_t base = (size_t)n*LSEQ;
  const float* up  = g_u  + base*DINC + d;
  const float* dtp = g_dt + base*DINC + d;
  const float* zp  = g_xz + base*(2*DINC) + DINC + d;
  const float* bp  = g_Bv + base;
  const float* cp  = g_Cv + base;
  float* yp = g_yf + base*DINC + d;
  float h = 0.f;
#pragma unroll 4
  for (int t=0;t<LSEQ;t++){
    const float uv  = up[(size_t)t*DINC];
    const float dtv = dtp[(size_t)t*DINC];
    const float zv  = zp[(size_t)t*(2*DINC)];
    const float bv  = bp[t];
    const float cv  = cp[t];
    const float a = expf(dtv*Ad);
    h = fmaf(h, a, dtv*bv*uv);
    const float y = fmaf(h, cv, uv*Dpd);
    yp[(size_t)t*DINC] = y * zv * sigf(zv);
  }
}

// K11: out_proj GEMM (131072x256 @ 128x256^T)
__global__ __launch_bounds__(256) void k11_outproj(const float* __restrict__ OW)
{
  __shared__ __align__(16) float As[8][128];
  __shared__ __align__(16) float Bs[8][128];
  const size_t m0 = (size_t)blockIdx.x*128;
  const int tid=threadIdx.x, tr=tid>>4, tc=tid&15, am=tid>>1, ak=(tid&1)*4;
  float acc[8][8]={};
  for (int k0=0;k0<DINC;k0+=8){
    float4 av = *(const float4*)&g_yf[(m0+am)*DINC + k0+ak];
    float4 wv = *(const float4*)&OW[(size_t)am*DINC + k0+ak];
    As[ak+0][am]=av.x; As[ak+1][am]=av.y; As[ak+2][am]=av.z; As[ak+3][am]=av.w;
    Bs[ak+0][am]=wv.x; Bs[ak+1][am]=wv.y; Bs[ak+2][am]=wv.z; Bs[ak+3][am]=wv.w;
    __syncthreads();
    mm_tile(As,Bs,acc,tr,tc);
    __syncthreads();
  }
#pragma unroll
  for (int i=0;i<8;i++){
    float* orow = g_Y4 + (m0 + tr*8 + i)*MDC + tc*8;
    float4 o0 = {acc[i][0],acc[i][1],acc[i][2],acc[i][3]};
    float4 o1 = {acc[i][4],acc[i][5],acc[i][6],acc[i][7]};
    *(float4*)&orow[0]=o0; *(float4*)&orow[4]=o1;
  }
}

// K12: pi gate GEMM + combine + 4-direction sum
__global__ __launch_bounds__(256) void k12_pi(const float* __restrict__ PW, const float* __restrict__ PB)
{
  __shared__ __align__(16) float As[8][128];
  __shared__ __align__(16) float Bs[8][128];
  const int b=blockIdx.y, l0=blockIdx.x*128, tid=threadIdx.x;
  const int tr=tid>>4, tc=tid&15, am=tid>>1, ak=(tid&1)*4;
  float ysumr[8][8]={};
  for (int dir=0;dir<4;dir++){
    const size_t rowbase = ((size_t)(dir*BQ+b))*LSEQ + l0;
    float acc[8][8]={};
    for (int k0=0;k0<2*MDC;k0+=8){
      const float* Asrc = (k0<MDC)? g_X4 : g_Y4;
      const int kk = k0 & (MDC-1);
      float4 av = *(const float4*)&Asrc[(rowbase+am)*MDC + kk+ak];
      float4 wv = *(const float4*)&PW[(size_t)am*(2*MDC) + k0+ak];
      As[ak+0][am]=av.x; As[ak+1][am]=av.y; As[ak+2][am]=av.z; As[ak+3][am]=av.w;
      Bs[ak+0][am]=wv.x; Bs[ak+1][am]=wv.y; Bs[ak+2][am]=wv.z; Bs[ak+3][am]=wv.w;
      __syncthreads();
      mm_tile(As,Bs,acc,tr,tc);
      __syncthreads();
    }
#pragma unroll
    for (int i=0;i<8;i++){
      const size_t row = rowbase + tr*8 + i;
#pragma unroll
      for (int j=0;j<8;j++){
        const int col = tc*8+j;
        const float pi = sigf(acc[i][j] + PB[col]);
        const float x4v = g_X4[row*MDC + col];
        const float y4v = g_Y4[row*MDC + col];
        ysumr[i][j] += y4v*pi + x4v*(1.f-pi);
      }
    }
  }
#pragma unroll
  for (int i=0;i<8;i++){
    float* orow = g_ysum + ((size_t)b*LSEQ + l0 + tr*8 + i)*MDC + tc*8;
    float4 o0 = {ysumr[i][0],ysumr[i][1],ysumr[i][2],ysumr[i][3]};
    float4 o1 = {ysumr[i][4],ysumr[i][5],ysumr[i][6],ysumr[i][7]};
    *(float4*)&orow[0]=o0; *(float4*)&orow[4]=o1;
  }
}

// K13: final conv1x1 over (f_scan + Fp)
__global__ __launch_bounds__(256) void k13_final(const float* __restrict__ FW, float* __restrict__ out)
{
  __shared__ __align__(16) float As[8][128];
  __shared__ __align__(16) float Bs[8][128];
  const int b=blockIdx.y, n0=blockIdx.x*128, tid=threadIdx.x;
  const int tr=tid>>4, tc=tid&15, am=tid>>1, ak=(tid&1)*4;
  float acc[8][8]={};
  const float* fpb = g_Fp + (size_t)b*MDC*NPOS;
  const float* ysb = g_ysum + (size_t)b*LSEQ*MDC;
  for (int k0=0;k0<MDC;k0+=8){
    float4 av = *(const float4*)&FW[(size_t)am*MDC + k0+ak];
    float4 yv = *(const float4*)&ysb[(size_t)(n0+am)*MDC + k0+ak];
    yv.x += fpb[(size_t)(k0+ak+0)*NPOS + n0+am];
    yv.y += fpb[(size_t)(k0+ak+1)*NPOS + n0+am];
    yv.z += fpb[(size_t)(k0+ak+2)*NPOS + n0+am];
    yv.w += fpb[(size_t)(k0+ak+3)*NPOS + n0+am];
    As[ak+0][am]=av.x; As[ak+1][am]=av.y; As[ak+2][am]=av.z; As[ak+3][am]=av.w;
    Bs[ak+0][am]=yv.x; Bs[ak+1][am]=yv.y; Bs[ak+2][am]=yv.z; Bs[ak+3][am]=yv.w;
    __syncthreads();
    mm_tile(As,Bs,acc,tr,tc);
    __syncthreads();
  }
#pragma unroll
  for (int i=0;i<8;i++){
    const int co = tr*8 + i;
    float* orow = out + ((size_t)b*NCH + co)*NPOS + n0 + tc*8;
    float4 o0 = {acc[i][0],acc[i][1],acc[i][2],acc[i][3]};
    float4 o1 = {acc[i][4],acc[i][5],acc[i][6],acc[i][7]};
    *(float4*)&orow[0]=o0; *(float4*)&orow[4]=o1;
  }
}

extern "C" void kernel_launch(void* const* d_in, const int* in_sizes, int n_in,
                              void* d_out, int out_size)
{
  const float* FT1=(const float*)d_in[0];
  const float* FT2=(const float*)d_in[1];
  const float* gpw=(const float*)d_in[2];
  const float* g1=(const float*)d_in[3];
  const float* b1=(const float*)d_in[4];
  const float* m1=(const float*)d_in[5];
  const float* v1=(const float*)d_in[6];
  const float* gcw=(const float*)d_in[7];
  const float* g2=(const float*)d_in[8];
  const float* b2=(const float*)d_in[9];
  const float* m2=(const float*)d_in[10];
  const float* v2=(const float*)d_in[11];
  const float* se1=(const float*)d_in[12];
  const float* se2=(const float*)d_in[13];
  const float* pjw=(const float*)d_in[14];
  const float* g3=(const float*)d_in[15];
  const float* b3=(const float*)d_in[16];
  const float* m3=(const float*)d_in[17];
  const float* v3=(const float*)d_in[18];
  const float* inw=(const float*)d_in[19];
  const float* c1w=(const float*)d_in[20];
  const float* c1b=(const float*)d_in[21];
  const float* xpw=(const float*)d_in[22];
  const float* dtw=(const float*)d_in[23];
  const float* dtb=(const float*)d_in[24];
  const float* alog=(const float*)d_in[25];
  const float* dp=(const float*)d_in[26];
  const float* opw=(const float*)d_in[27];
  const float* piw=(const float*)d_in[28];
  const float* pib=(const float*)d_in[29];
  const float* fw=(const float*)d_in[30];
  float* out=(float*)d_out;

  k1_conv1  <<<dim3(32,4,8),256>>>(FT1,FT2,gpw,g1,b1,m1,v1);
  k2_dw     <<<BQ*ICC,256>>>(gcw,g2,b2,m2,v2);
  k_se_reduce<<<BQ*UPC,256>>>();
  k_se_mlp  <<<BQ,256>>>(se1,se2);
  k4_proj   <<<dim3(32,1,8),256>>>(pjw,g3,b3,m3,v3);
  k5_x4     <<<(NSEQ*LSEQ*MDC/4)/256,256>>>();
  k6_inproj <<<dim3(4,1024),256>>>(inw);
  k7_conv1d <<<(NSEQ*LSEQ*DINC/4)/256,256>>>(c1w,c1b);
  k8_xproj  <<<NSEQ*LSEQ/8,256>>>(xpw);
  k9_dt     <<<NSEQ*LSEQ/8,256>>>(dtw,dtb);
  k10_scan  <<<NSEQ,256>>>(alog,dp);
  k11_outproj<<<NSEQ*LSEQ/128,256>>>(opw);
  k12_pi    <<<dim3(32,8),256>>>(piw,pib);
  k13_final <<<dim3(32,8),256>>>(fw,out);
}

// round 4
// speedup vs baseline: 1.3203x; 1.3203x over previous
#include <cuda_runtime.h>
#include <math.h>

#define BQ 8
#define NCH 128
#define NPOS 4096
#define INPC 256
#define UPC 1024
#define MDC 128
#define ICC 512
#define DINC 256
#define LSEQ 4096
#define NSEQ 32
#define EPSV 1e-5f

__device__ __align__(16) float g_x1 [(size_t)BQ*ICC*NPOS];
__device__ __align__(16) float g_x2 [(size_t)BQ*ICC*NPOS];
__device__ __align__(16) float g_s0 [BQ*UPC];
__device__ __align__(16) float g_s  [BQ*UPC];
__device__ __align__(16) float g_Fp [(size_t)BQ*MDC*NPOS];
__device__ __align__(16) float g_X4 [(size_t)NSEQ*LSEQ*MDC];
__device__ __align__(16) float g_xz [(size_t)NSEQ*LSEQ*2*DINC];
__device__ __align__(16) float g_u  [(size_t)NSEQ*LSEQ*DINC];
__device__ __align__(16) float g_dbl[(size_t)NSEQ*LSEQ*10];
__device__ __align__(16) float g_dt [(size_t)NSEQ*LSEQ*DINC];
__device__ __align__(16) float g_Bv [NSEQ*LSEQ];
__device__ __align__(16) float g_Cv [NSEQ*LSEQ];
__device__ __align__(16) float g_yf [(size_t)NSEQ*LSEQ*DINC];
__device__ __align__(16) float g_Y4 [(size_t)NSEQ*LSEQ*MDC];
__device__ __align__(16) float g_ysum[(size_t)BQ*LSEQ*MDC];

__device__ __forceinline__ float sigf(float x){ return 1.f/(1.f+__expf(-x)); }

// ---- common 128x128 KT=16 tile machinery ----
#define TDEF const int tid=threadIdx.x, tr=tid>>4, tc=tid&15, am=tid>>1, ak=(tid&1)*8, bk=tid>>4, bn=(tid&15)*8;
#define ROFF(i) (tr*4 + ((i)&3) + (((i)>>2)<<6))

__device__ __forceinline__ void sts_trans(float (*S)[132], int ak, int am, float4 r0, float4 r1){
  S[ak+0][am]=r0.x; S[ak+1][am]=r0.y; S[ak+2][am]=r0.z; S[ak+3][am]=r0.w;
  S[ak+4][am]=r1.x; S[ak+5][am]=r1.y; S[ak+6][am]=r1.z; S[ak+7][am]=r1.w;
}
__device__ __forceinline__ void sts_row(float (*S)[132], int bk, int bn, float4 r0, float4 r1){
  *(float4*)&S[bk][bn]=r0; *(float4*)&S[bk][bn+4]=r1;
}
__device__ __forceinline__ void mm16(const float (*As)[132], const float (*Bs)[132],
                                     float (&acc)[8][8], int tr, int tc){
#pragma unroll
  for (int k=0;k<16;k++){
    float4 a0=*(const float4*)&As[k][tr*4];
    float4 a1=*(const float4*)&As[k][tr*4+64];
    float4 b0=*(const float4*)&Bs[k][tc*4];
    float4 b1=*(const float4*)&Bs[k][tc*4+64];
    float av[8]={a0.x,a0.y,a0.z,a0.w,a1.x,a1.y,a1.z,a1.w};
    float bv[8]={b0.x,b0.y,b0.z,b0.w,b1.x,b1.y,b1.z,b1.w};
#pragma unroll
    for (int i=0;i<8;i++)
#pragma unroll
      for (int j=0;j<8;j++) acc[i][j]=fmaf(av[i],bv[j],acc[i][j]);
  }
}

// K1: conv1x1 (256->512) + BN1 + ReLU
__global__ __launch_bounds__(256,2) void k1_conv1(
    const float* __restrict__ FT1, const float* __restrict__ FT2,
    const float* __restrict__ W,  const float* __restrict__ g1,
    const float* __restrict__ b1, const float* __restrict__ m1,
    const float* __restrict__ v1)
{
  __shared__ __align__(16) float As[2][16][132];
  __shared__ __align__(16) float Bs[2][16][132];
  TDEF;
  const int b=blockIdx.z, m0=blockIdx.y*128, n0=blockIdx.x*128;
  const float* f1=FT1+(size_t)b*NCH*NPOS;
  const float* f2=FT2+(size_t)b*NCH*NPOS;
  float acc[8][8]={};
  float4 ra0,ra1,rb0,rb1;
#define K1_LDG(k0) { \
    ra0=*(const float4*)&W[(size_t)(m0+am)*INPC+(k0)+ak]; \
    ra1=*(const float4*)&W[(size_t)(m0+am)*INPC+(k0)+ak+4]; \
    const int ci=(k0)+bk; \
    const float* s=(ci<NCH)?(f1+(size_t)ci*NPOS):(f2+(size_t)(ci-NCH)*NPOS); \
    rb0=*(const float4*)&s[n0+bn]; rb1=*(const float4*)&s[n0+bn+4]; }
  K1_LDG(0);
  sts_trans(As[0],ak,am,ra0,ra1); sts_row(Bs[0],bk,bn,rb0,rb1);
  __syncthreads();
  for (int it=0;it<16;it++){
    const int p=it&1;
    if (it<15) K1_LDG((it+1)*16);
    mm16(As[p],Bs[p],acc,tr,tc);
    if (it<15){ sts_trans(As[1-p],ak,am,ra0,ra1); sts_row(Bs[1-p],bk,bn,rb0,rb1); }
    __syncthreads();
  }
#pragma unroll
  for (int i=0;i<8;i++){
    const int co=m0+ROFF(i);
    const float sc=g1[co]*rsqrtf(v1[co]+EPSV);
    const float bi=b1[co]-m1[co]*sc;
    float* orow=g_x1+((size_t)b*ICC+co)*NPOS+n0;
    float4 o0,o1;
    o0.x=fmaxf(fmaf(acc[i][0],sc,bi),0.f); o0.y=fmaxf(fmaf(acc[i][1],sc,bi),0.f);
    o0.z=fmaxf(fmaf(acc[i][2],sc,bi),0.f); o0.w=fmaxf(fmaf(acc[i][3],sc,bi),0.f);
    o1.x=fmaxf(fmaf(acc[i][4],sc,bi),0.f); o1.y=fmaxf(fmaf(acc[i][5],sc,bi),0.f);
    o1.z=fmaxf(fmaf(acc[i][6],sc,bi),0.f); o1.w=fmaxf(fmaf(acc[i][7],sc,bi),0.f);
    *(float4*)&orow[tc*4]=o0; *(float4*)&orow[tc*4+64]=o1;
  }
}

// K2: depthwise 3x3 + BN2 + ReLU
__global__ __launch_bounds__(256) void k2_dw(
    const float* __restrict__ W3, const float* __restrict__ g2,
    const float* __restrict__ b2, const float* __restrict__ m2,
    const float* __restrict__ v2)
{
  const int bc=blockIdx.x, c=bc&(ICC-1);
  const float* plane=g_x1+(size_t)bc*NPOS;
  float w[9];
#pragma unroll
  for (int i=0;i<9;i++) w[i]=W3[c*9+i];
  const float sc=g2[c]*rsqrtf(v2[c]+EPSV);
  const float bi=b2[c]-m2[c]*sc;
  float* outp=g_x2+(size_t)bc*NPOS;
  for (int p=threadIdx.x;p<NPOS;p+=256){
    const int h=p>>6, ww=p&63;
    float a=0.f;
#pragma unroll
    for (int di=-1;di<=1;di++){
      const int hh=h+di;
      if ((unsigned)hh<64u){
#pragma unroll
        for (int dj=-1;dj<=1;dj++){
          const int wq=ww+dj;
          if ((unsigned)wq<64u) a=fmaf(w[(di+1)*3+dj+1],plane[hh*64+wq],a);
        }
      }
    }
    outp[p]=fmaxf(fmaf(a,sc,bi),0.f);
  }
}

// SE mean
__global__ __launch_bounds__(256) void k_se_reduce()
{
  __shared__ float red[256];
  const int bc=blockIdx.x, b=bc>>10, c=bc&1023;
  const float* plane=(c<ICC)?(g_x1+((size_t)b*ICC+c)*NPOS):(g_x2+((size_t)b*ICC+(c-ICC))*NPOS);
  float s=0.f;
  for (int p=threadIdx.x;p<NPOS;p+=256) s+=plane[p];
  red[threadIdx.x]=s; __syncthreads();
  for (int o=128;o>0;o>>=1){ if(threadIdx.x<o) red[threadIdx.x]+=red[threadIdx.x+o]; __syncthreads(); }
  if (threadIdx.x==0) g_s0[b*UPC+c]=red[0]*(1.f/NPOS);
}

// SE MLP: grid (8,4)
__global__ __launch_bounds__(256) void k_se_mlp(const float* __restrict__ w1, const float* __restrict__ w2)
{
  __shared__ float s0[1024];
  __shared__ float part[256];
  __shared__ float hid[64];
  const int b=blockIdx.x, tid=threadIdx.x;
  for (int c=tid;c<1024;c+=256) s0[c]=g_s0[b*UPC+c];
  __syncthreads();
  const int j=tid>>2, q=tid&3;
  float p=0.f;
  const float* w1r=w1+j*1024+q*256;
  const float* s0r=s0+q*256;
#pragma unroll 8
  for (int c=0;c<256;c++) p=fmaf(s0r[c],w1r[c],p);
  part[tid]=p; __syncthreads();
  if (tid<64) hid[tid]=fmaxf(part[tid*4]+part[tid*4+1]+part[tid*4+2]+part[tid*4+3],0.f);
  __syncthreads();
  const int c=blockIdx.y*256+tid;
  const float4* w2r=(const float4*)(w2+c*64);
  float a=0.f;
#pragma unroll
  for (int jj=0;jj<16;jj++){
    float4 wv=w2r[jj];
    a=fmaf(hid[jj*4],wv.x,a); a=fmaf(hid[jj*4+1],wv.y,a);
    a=fmaf(hid[jj*4+2],wv.z,a); a=fmaf(hid[jj*4+3],wv.w,a);
  }
  g_s[b*UPC+c]=sigf(a);
}

// K4: proj conv1x1 (1024->128) + SE scale + BN3
__global__ __launch_bounds__(256,2) void k4_proj(
    const float* __restrict__ PW, const float* __restrict__ g3,
    const float* __restrict__ b3, const float* __restrict__ m3,
    const float* __restrict__ v3)
{
  __shared__ __align__(16) float As[2][16][132];
  __shared__ __align__(16) float Bs[2][16][132];
  TDEF;
  const int b=blockIdx.z, n0=blockIdx.x*128;
  float acc[8][8]={};
  float4 ra0,ra1,rb0,rb1;
#define K4_LDG(k0) { \
    ra0=*(const float4*)&PW[(size_t)am*UPC+(k0)+ak]; \
    ra1=*(const float4*)&PW[(size_t)am*UPC+(k0)+ak+4]; \
    const int ci=(k0)+bk; \
    const float* s=(ci<ICC)?(g_x1+((size_t)b*ICC+ci)*NPOS):(g_x2+((size_t)b*ICC+(ci-ICC))*NPOS); \
    const float sv=g_s[b*UPC+ci]; \
    rb0=*(const float4*)&s[n0+bn]; rb1=*(const float4*)&s[n0+bn+4]; \
    rb0.x*=sv; rb0.y*=sv; rb0.z*=sv; rb0.w*=sv; \
    rb1.x*=sv; rb1.y*=sv; rb1.z*=sv; rb1.w*=sv; }
  K4_LDG(0);
  sts_trans(As[0],ak,am,ra0,ra1); sts_row(Bs[0],bk,bn,rb0,rb1);
  __syncthreads();
  for (int it=0;it<64;it++){
    const int p=it&1;
    if (it<63) K4_LDG((it+1)*16);
    mm16(As[p],Bs[p],acc,tr,tc);
    if (it<63){ sts_trans(As[1-p],ak,am,ra0,ra1); sts_row(Bs[1-p],bk,bn,rb0,rb1); }
    __syncthreads();
  }
#pragma unroll
  for (int i=0;i<8;i++){
    const int d=ROFF(i);
    const float sc=g3[d]*rsqrtf(v3[d]+EPSV);
    const float bi=b3[d]-m3[d]*sc;
    float* orow=g_Fp+((size_t)b*MDC+d)*NPOS+n0;
    float4 o0,o1;
    o0.x=fmaf(acc[i][0],sc,bi); o0.y=fmaf(acc[i][1],sc,bi);
    o0.z=fmaf(acc[i][2],sc,bi); o0.w=fmaf(acc[i][3],sc,bi);
    o1.x=fmaf(acc[i][4],sc,bi); o1.y=fmaf(acc[i][5],sc,bi);
    o1.z=fmaf(acc[i][6],sc,bi); o1.w=fmaf(acc[i][7],sc,bi);
    *(float4*)&orow[tc*4]=o0; *(float4*)&orow[tc*4+64]=o1;
  }
}

// K5: build X4
__global__ __launch_bounds__(256) void k5_x4()
{
  const int gid=blockIdx.x*256+threadIdx.x;
  const int d4=(gid&31)*4;
  const int l=(gid>>5)&4095;
  const int n=gid>>17;
  const int dir=n>>3, b=n&7;
  int p;
  if (dir==0)      p=l;
  else if (dir==1) p=(l&~63)+63-(l&63);
  else if (dir==2) p=((l&63)<<6)+(l>>6);
  else             p=((63-(l&63))<<6)+(l>>6);
  const float* fp=g_Fp+(size_t)b*MDC*NPOS+p;
  float4 v;
  v.x=fp[(size_t)(d4+0)*NPOS];
  v.y=fp[(size_t)(d4+1)*NPOS];
  v.z=fp[(size_t)(d4+2)*NPOS];
  v.w=fp[(size_t)(d4+3)*NPOS];
  *(float4*)&g_X4[((size_t)n*LSEQ+l)*MDC+d4]=v;
}

// K6: in_proj GEMM (131072x128 @ 512x128^T)
__global__ __launch_bounds__(256,2) void k6_inproj(const float* __restrict__ Wi)
{
  __shared__ __align__(16) float As[2][16][132];
  __shared__ __align__(16) float Bs[2][16][132];
  TDEF;
  const int n0=blockIdx.x*128;
  const size_t m0=(size_t)blockIdx.y*128;
  float acc[8][8]={};
  float4 ra0,ra1,rb0,rb1;
#define K6_LDG(k0) { \
    ra0=*(const float4*)&g_X4[(m0+am)*MDC+(k0)+ak]; \
    ra1=*(const float4*)&g_X4[(m0+am)*MDC+(k0)+ak+4]; \
    rb0=*(const float4*)&Wi[(size_t)(n0+am)*MDC+(k0)+ak]; \
    rb1=*(const float4*)&Wi[(size_t)(n0+am)*MDC+(k0)+ak+4]; }
  K6_LDG(0);
  sts_trans(As[0],ak,am,ra0,ra1); sts_trans(Bs[0],ak,am,rb0,rb1);
  __syncthreads();
  for (int it=0;it<8;it++){
    const int p=it&1;
    if (it<7) K6_LDG((it+1)*16);
    mm16(As[p],Bs[p],acc,tr,tc);
    if (it<7){ sts_trans(As[1-p],ak,am,ra0,ra1); sts_trans(Bs[1-p],ak,am,rb0,rb1); }
    __syncthreads();
  }
#pragma unroll
  for (int i=0;i<8;i++){
    float* orow=g_xz+(m0+ROFF(i))*(2*DINC)+n0;
    float4 o0={acc[i][0],acc[i][1],acc[i][2],acc[i][3]};
    float4 o1={acc[i][4],acc[i][5],acc[i][6],acc[i][7]};
    *(float4*)&orow[tc*4]=o0; *(float4*)&orow[tc*4+64]=o1;
  }
}

// K7: causal conv1d + SiLU
__global__ __launch_bounds__(256) void k7_conv1d(const float* __restrict__ CW, const float* __restrict__ CB)
{
  const int gid=blockIdx.x*256+threadIdx.x;
  const int d4=(gid&63)*4;
  const int l=(gid>>6)&4095;
  const int n=gid>>18;
  const float* base=g_xz+(size_t)n*LSEQ*(2*DINC)+d4;
  float4 acc={CB[d4],CB[d4+1],CB[d4+2],CB[d4+3]};
  float w[4][4];
#pragma unroll
  for (int i=0;i<4;i++){
    float4 wr=*(const float4*)&CW[(d4+i)*4];
    w[i][0]=wr.x; w[i][1]=wr.y; w[i][2]=wr.z; w[i][3]=wr.w;
  }
#pragma unroll
  for (int k=0;k<4;k++){
    const int lt=l-3+k;
    if (lt>=0){
      float4 x=*(const float4*)&base[(size_t)lt*(2*DINC)];
      acc.x=fmaf(w[0][k],x.x,acc.x); acc.y=fmaf(w[1][k],x.y,acc.y);
      acc.z=fmaf(w[2][k],x.z,acc.z); acc.w=fmaf(w[3][k],x.w,acc.w);
    }
  }
  acc.x*=sigf(acc.x); acc.y*=sigf(acc.y);
  acc.z*=sigf(acc.z); acc.w*=sigf(acc.w);
  *(float4*)&g_u[((size_t)n*LSEQ+l)*DINC+d4]=acc;
}

// K8: x_proj
__global__ __launch_bounds__(256) void k8_xproj(const float* __restrict__ XW)
{
  __shared__ float xw[10*DINC];
  const int tid=threadIdx.x;
  for (int i=tid;i<10*DINC;i+=256) xw[i]=XW[i];
  __syncthreads();
  const int warp=tid>>5, lane=tid&31;
  const size_t r=(size_t)blockIdx.x*8+warp;
  const float* urow=g_u+r*DINC;
  float uv[8];
#pragma unroll
  for (int i=0;i<8;i++) uv[i]=urow[lane+32*i];
#pragma unroll
  for (int j=0;j<10;j++){
    float p=0.f;
#pragma unroll
    for (int i=0;i<8;i++) p=fmaf(uv[i],xw[j*DINC+lane+32*i],p);
#pragma unroll
    for (int o=16;o>0;o>>=1) p+=__shfl_xor_sync(0xffffffffu,p,o);
    if (lane==0) g_dbl[r*10+j]=p;
  }
}

// K9: dt softplus
__global__ __launch_bounds__(256) void k9_dt(const float* __restrict__ DTW, const float* __restrict__ DTB)
{
  const int d=threadIdx.x;
  float w[8];
#pragma unroll
  for (int q=0;q<8;q++) w[q]=DTW[d*8+q];
  const float bb=DTB[d];
  const size_t r0=(size_t)blockIdx.x*8;
  for (int rr=0;rr<8;rr++){
    const size_t r=r0+rr;
    const float* db=g_dbl+r*10;
    float pre=bb;
#pragma unroll
    for (int q=0;q<8;q++) pre=fmaf(db[q],w[q],pre);
    const float sp=(pre>20.f)?pre:logf(1.f+__expf(pre));
    g_dt[r*DINC+d]=sp;
    if (d==0){ g_Bv[r]=db[8]; g_Cv[r]=db[9]; }
  }
}

// K10: selective scan
__global__ __launch_bounds__(256) void k10_scan(const float* __restrict__ AL, const float* __restrict__ DP)
{
  const int n=blockIdx.x, d=threadIdx.x;
  const float Ad=-__expf(AL[d]);
  const float Dpd=DP[d];
  const size_t base=(size_t)n*LSEQ;
  const float* up =g_u +base*DINC+d;
  const float* dtp=g_dt+base*DINC+d;
  const float* zp =g_xz+base*(2*DINC)+DINC+d;
  const float* bp =g_Bv+base;
  const float* cp =g_Cv+base;
  float* yp=g_yf+base*DINC+d;
  float h=0.f;
#pragma unroll 4
  for (int t=0;t<LSEQ;t++){
    const float uv =up [(size_t)t*DINC];
    const float dtv=dtp[(size_t)t*DINC];
    const float zv =zp [(size_t)t*(2*DINC)];
    const float bv =bp[t];
    const float cv =cp[t];
    const float a=__expf(dtv*Ad);
    h=fmaf(h,a,dtv*bv*uv);
    const float y=fmaf(h,cv,uv*Dpd);
    yp[(size_t)t*DINC]=y*zv*sigf(zv);
  }
}

// K11: out_proj GEMM
__global__ __launch_bounds__(256,2) void k11_outproj(const float* __restrict__ OW)
{
  __shared__ __align__(16) float As[2][16][132];
  __shared__ __align__(16) float Bs[2][16][132];
  TDEF;
  const size_t m0=(size_t)blockIdx.x*128;
  float acc[8][8]={};
  float4 ra0,ra1,rb0,rb1;
#define K11_LDG(k0) { \
    ra0=*(const float4*)&g_yf[(m0+am)*DINC+(k0)+ak]; \
    ra1=*(const float4*)&g_yf[(m0+am)*DINC+(k0)+ak+4]; \
    rb0=*(const float4*)&OW[(size_t)am*DINC+(k0)+ak]; \
    rb1=*(const float4*)&OW[(size_t)am*DINC+(k0)+ak+4]; }
  K11_LDG(0);
  sts_trans(As[0],ak,am,ra0,ra1); sts_trans(Bs[0],ak,am,rb0,rb1);
  __syncthreads();
  for (int it=0;it<16;it++){
    const int p=it&1;
    if (it<15) K11_LDG((it+1)*16);
    mm16(As[p],Bs[p],acc,tr,tc);
    if (it<15){ sts_trans(As[1-p],ak,am,ra0,ra1); sts_trans(Bs[1-p],ak,am,rb0,rb1); }
    __syncthreads();
  }
#pragma unroll
  for (int i=0;i<8;i++){
    float* orow=g_Y4+(m0+ROFF(i))*MDC;
    float4 o0={acc[i][0],acc[i][1],acc[i][2],acc[i][3]};
    float4 o1={acc[i][4],acc[i][5],acc[i][6],acc[i][7]};
    *(float4*)&orow[tc*4]=o0; *(float4*)&orow[tc*4+64]=o1;
  }
}

// K12: pi gate + combine + 4-direction sum
__global__ __launch_bounds__(256,2) void k12_pi(const float* __restrict__ PW, const float* __restrict__ PB)
{
  __shared__ __align__(16) float As[2][16][132];
  __shared__ __align__(16) float Bs[2][16][132];
  TDEF;
  const int b=blockIdx.y, l0=blockIdx.x*128;
  float ysumr[8][8]={};
  for (int dir=0;dir<4;dir++){
    const size_t rowbase=((size_t)(dir*BQ+b))*LSEQ+l0;
    float acc[8][8]={};
    float4 ra0,ra1,rb0,rb1;
#define K12_LDG(k0) { \
      const int kk=(k0)+ak; \
      const float* asrc=(kk<MDC)?g_X4:g_Y4; \
      const int km=kk&(MDC-1); \
      ra0=*(const float4*)&asrc[(rowbase+am)*MDC+km]; \
      ra1=*(const float4*)&asrc[(rowbase+am)*MDC+km+4]; \
      rb0=*(const float4*)&PW[(size_t)am*(2*MDC)+(k0)+ak]; \
      rb1=*(const float4*)&PW[(size_t)am*(2*MDC)+(k0)+ak+4]; }
    K12_LDG(0);
    sts_trans(As[0],ak,am,ra0,ra1); sts_trans(Bs[0],ak,am,rb0,rb1);
    __syncthreads();
    for (int it=0;it<16;it++){
      const int p=it&1;
      if (it<15) K12_LDG((it+1)*16);
      mm16(As[p],Bs[p],acc,tr,tc);
      if (it<15){ sts_trans(As[1-p],ak,am,ra0,ra1); sts_trans(Bs[1-p],ak,am,rb0,rb1); }
      __syncthreads();
    }
#pragma unroll
    for (int i=0;i<8;i++){
      const size_t row=rowbase+ROFF(i);
      const float4 x40=*(const float4*)&g_X4[row*MDC+tc*4];
      const float4 x41=*(const float4*)&g_X4[row*MDC+tc*4+64];
      const float4 y40=*(const float4*)&g_Y4[row*MDC+tc*4];
      const float4 y41=*(const float4*)&g_Y4[row*MDC+tc*4+64];
      const float xa[8]={x40.x,x40.y,x40.z,x40.w,x41.x,x41.y,x41.z,x41.w};
      const float ya[8]={y40.x,y40.y,y40.z,y40.w,y41.x,y41.y,y41.z,y41.w};
#pragma unroll
      for (int j=0;j<8;j++){
        const int col=tc*4+(j&3)+((j>>2)<<6);
        const float pi=sigf(acc[i][j]+PB[col]);
        ysumr[i][j]+=ya[j]*pi+xa[j]*(1.f-pi);
      }
    }
    __syncthreads();
  }
#pragma unroll
  for (int i=0;i<8;i++){
    float* orow=g_ysum+((size_t)b*LSEQ+l0+ROFF(i))*MDC;
    float4 o0={ysumr[i][0],ysumr[i][1],ysumr[i][2],ysumr[i][3]};
    float4 o1={ysumr[i][4],ysumr[i][5],ysumr[i][6],ysumr[i][7]};
    *(float4*)&orow[tc*4]=o0; *(float4*)&orow[tc*4+64]=o1;
  }
}

// K13: final conv1x1 over (f_scan + Fp)
__global__ __launch_bounds__(256,2) void k13_final(const float* __restrict__ FW, float* __restrict__ out)
{
  __shared__ __align__(16) float As[2][16][132];
  __shared__ __align__(16) float Bs[2][16][132];
  TDEF;
  const int b=blockIdx.y, n0=blockIdx.x*128;
  const float* fpb=g_Fp+(size_t)b*MDC*NPOS;
  const float* ysb=g_ysum+(size_t)b*LSEQ*MDC;
  float acc[8][8]={};
  float4 ra0,ra1,rb0,rb1;
#define K13_LDG(k0) { \
    ra0=*(const float4*)&FW[(size_t)am*MDC+(k0)+ak]; \
    ra1=*(const float4*)&FW[(size_t)am*MDC+(k0)+ak+4]; \
    rb0=*(const float4*)&ysb[(size_t)(n0+am)*MDC+(k0)+ak]; \
    rb1=*(const float4*)&ysb[(size_t)(n0+am)*MDC+(k0)+ak+4]; \
    rb0.x+=fpb[(size_t)((k0)+ak+0)*NPOS+n0+am]; \
    rb0.y+=fpb[(size_t)((k0)+ak+1)*NPOS+n0+am]; \
    rb0.z+=fpb[(size_t)((k0)+ak+2)*NPOS+n0+am]; \
    rb0.w+=fpb[(size_t)((k0)+ak+3)*NPOS+n0+am]; \
    rb1.x+=fpb[(size_t)((k0)+ak+4)*NPOS+n0+am]; \
    rb1.y+=fpb[(size_t)((k0)+ak+5)*NPOS+n0+am]; \
    rb1.z+=fpb[(size_t)((k0)+ak+6)*NPOS+n0+am]; \
    rb1.w+=fpb[(size_t)((k0)+ak+7)*NPOS+n0+am]; }
  K13_LDG(0);
  sts_trans(As[0],ak,am,ra0,ra1); sts_trans(Bs[0],ak,am,rb0,rb1);
  __syncthreads();
  for (int it=0;it<8;it++){
    const int p=it&1;
    if (it<7) K13_LDG((it+1)*16);
    mm16(As[p],Bs[p],acc,tr,tc);
    if (it<7){ sts_trans(As[1-p],ak,am,ra0,ra1); sts_trans(Bs[1-p],ak,am,rb0,rb1); }
    __syncthreads();
  }
#pragma unroll
  for (int i=0;i<8;i++){
    const int co=ROFF(i);
    float* orow=out+((size_t)b*NCH+co)*NPOS+n0;
    float4 o0={acc[i][0],acc[i][1],acc[i][2],acc[i][3]};
    float4 o1={acc[i][4],acc[i][5],acc[i][6],acc[i][7]};
    *(float4*)&orow[tc*4]=o0; *(float4*)&orow[tc*4+64]=o1;
  }
}

extern "C" void kernel_launch(void* const* d_in, const int* in_sizes, int n_in,
                              void* d_out, int out_size)
{
  const float* FT1=(const float*)d_in[0];
  const float* FT2=(const float*)d_in[1];
  const float* gpw=(const float*)d_in[2];
  const float* g1=(const float*)d_in[3];
  const float* b1=(const float*)d_in[4];
  const float* m1=(const float*)d_in[5];
  const float* v1=(const float*)d_in[6];
  const float* gcw=(const float*)d_in[7];
  const float* g2=(const float*)d_in[8];
  const float* b2=(const float*)d_in[9];
  const float* m2=(const float*)d_in[10];
  const float* v2=(const float*)d_in[11];
  const float* se1=(const float*)d_in[12];
  const float* se2=(const float*)d_in[13];
  const float* pjw=(const float*)d_in[14];
  const float* g3=(const float*)d_in[15];
  const float* b3=(const float*)d_in[16];
  const float* m3=(const float*)d_in[17];
  const float* v3=(const float*)d_in[18];
  const float* inw=(const float*)d_in[19];
  const float* c1w=(const float*)d_in[20];
  const float* c1b=(const float*)d_in[21];
  const float* xpw=(const float*)d_in[22];
  const float* dtw=(const float*)d_in[23];
  const float* dtb=(const float*)d_in[24];
  const float* alog=(const float*)d_in[25];
  const float* dp=(const float*)d_in[26];
  const float* opw=(const float*)d_in[27];
  const float* piw=(const float*)d_in[28];
  const float* pib=(const float*)d_in[29];
  const float* fw=(const float*)d_in[30];
  float* out=(float*)d_out;

  k1_conv1   <<<dim3(32,4,8),256>>>(FT1,FT2,gpw,g1,b1,m1,v1);
  k2_dw      <<<BQ*ICC,256>>>(gcw,g2,b2,m2,v2);
  k_se_reduce<<<BQ*UPC,256>>>();
  k_se_mlp   <<<dim3(8,4),256>>>(se1,se2);
  k4_proj    <<<dim3(32,1,8),256>>>(pjw,g3,b3,m3,v3);
  k5_x4      <<<(NSEQ*LSEQ*MDC/4)/256,256>>>();
  k6_inproj  <<<dim3(4,1024),256>>>(inw);
  k7_conv1d  <<<(NSEQ*LSEQ*DINC/4)/256,256>>>(c1w,c1b);
  k8_xproj   <<<NSEQ*LSEQ/8,256>>>(xpw);
  k9_dt      <<<NSEQ*LSEQ/8,256>>>(dtw,dtb);
  k10_scan   <<<NSEQ,256>>>(alog,dp);
  k11_outproj<<<NSEQ*LSEQ/128,256>>>(opw);
  k12_pi     <<<dim3(32,8),256>>>(piw,pib);
  k13_final  <<<dim3(32,8),256>>>(fw,out);
}

// round 5
// speedup vs baseline: 1.4647x; 1.1094x over previous
#include <cuda_runtime.h>
#include <cuda_bf16.h>
#include <math.h>

#define BQ 8
#define NCH 128
#define NPOS 4096
#define INPC 256
#define UPC 1024
#define MDC 128
#define ICC 512
#define DINC 256
#define LSEQ 4096
#define NSEQ 32
#define EPSV 1e-5f

__device__ __align__(16) float g_x1 [(size_t)BQ*ICC*NPOS];
__device__ __align__(16) float g_x2 [(size_t)BQ*ICC*NPOS];
__device__ __align__(16) float g_s0 [BQ*UPC];
__device__ __align__(16) float g_s  [BQ*UPC];
__device__ __align__(16) float g_Fp [(size_t)BQ*MDC*NPOS];
__device__ __align__(16) float g_X4 [(size_t)NSEQ*LSEQ*MDC];
__device__ __align__(16) float g_xz [(size_t)NSEQ*LSEQ*2*DINC];
__device__ __align__(16) float g_u  [(size_t)NSEQ*LSEQ*DINC];
__device__ __align__(16) float g_dbl[(size_t)NSEQ*LSEQ*10];
__device__ __align__(16) float g_dt [(size_t)NSEQ*LSEQ*DINC];
__device__ __align__(16) float g_Bv [NSEQ*LSEQ];
__device__ __align__(16) float g_Cv [NSEQ*LSEQ];
__device__ __align__(16) float g_yf [(size_t)NSEQ*LSEQ*DINC];
__device__ __align__(16) float g_Y4 [(size_t)NSEQ*LSEQ*MDC];
__device__ __align__(16) float g_ysum[(size_t)BQ*LSEQ*MDC];

__device__ __forceinline__ float sigf(float x){ return 1.f/(1.f+__expf(-x)); }

// ---------------- bf16 split MMA machinery ----------------
__device__ __forceinline__ void mma_bf16(float* d, const unsigned* a, const unsigned* b){
  asm volatile("mma.sync.aligned.m16n8k16.row.col.f32.bf16.bf16.f32 "
    "{%0,%1,%2,%3},{%4,%5,%6,%7},{%8,%9},{%0,%1,%2,%3};"
    : "+f"(d[0]),"+f"(d[1]),"+f"(d[2]),"+f"(d[3])
    : "r"(a[0]),"r"(a[1]),"r"(a[2]),"r"(a[3]),"r"(b[0]),"r"(b[1]));
}
__device__ __forceinline__ void cvst(float4 v, __nv_bfloat16* ph, __nv_bfloat16* pl){
  __nv_bfloat162 h0,h1,l0,l1;
  h0.x=__float2bfloat16(v.x); h0.y=__float2bfloat16(v.y);
  h1.x=__float2bfloat16(v.z); h1.y=__float2bfloat16(v.w);
  l0.x=__float2bfloat16(v.x-__bfloat162float(h0.x));
  l0.y=__float2bfloat16(v.y-__bfloat162float(h0.y));
  l1.x=__float2bfloat16(v.z-__bfloat162float(h1.x));
  l1.y=__float2bfloat16(v.w-__bfloat162float(h1.y));
  *(__nv_bfloat162*)ph=h0; *(__nv_bfloat162*)(ph+2)=h1;
  *(__nv_bfloat162*)pl=l0; *(__nv_bfloat162*)(pl+2)=l1;
}
__device__ __forceinline__ void ldfragA(const __nv_bfloat16 (*A)[40], int r, int kc, unsigned* a){
  a[0]=*(const unsigned*)&A[r][kc];
  a[1]=*(const unsigned*)&A[r+8][kc];
  a[2]=*(const unsigned*)&A[r][kc+8];
  a[3]=*(const unsigned*)&A[r+8][kc+8];
}
__device__ __forceinline__ void ldfragB_nk(const __nv_bfloat16 (*B)[40], int nr, int kc, unsigned* bb){
  bb[0]=*(const unsigned*)&B[nr][kc];
  bb[1]=*(const unsigned*)&B[nr][kc+8];
}
__device__ __forceinline__ void ldfragB_kn(const __nv_bfloat16 (*B)[136], int nr, int kc, unsigned* bb){
  unsigned x0=*(const unsigned short*)&B[kc][nr];
  unsigned x1=*(const unsigned short*)&B[kc+1][nr];
  bb[0]=x0|(x1<<16);
  x0=*(const unsigned short*)&B[kc+8][nr];
  x1=*(const unsigned short*)&B[kc+9][nr];
  bb[1]=x0|(x1<<16);
}

#define WDEF const int tid=threadIdx.x, wid=tid>>5, lane=tid&31, gq=lane>>2, tq=lane&3; \
  const int wm=(wid>>1)*32, wn=(wid&1)*64;

#define COMPUTE_NK() \
    for (int s=0;s<32;s+=16){ \
      const int kc=s+2*tq; \
      unsigned ah0[4],ah1[4],al0[4],al1[4]; \
      ldfragA(Ah,wm+gq,kc,ah0); ldfragA(Ah,wm+16+gq,kc,ah1); \
      ldfragA(Al,wm+gq,kc,al0); ldfragA(Al,wm+16+gq,kc,al1); \
      for(int j=0;j<8;j++){ \
        unsigned bh[2],bl[2]; \
        ldfragB_nk(Bh,wn+j*8+gq,kc,bh); ldfragB_nk(Bl,wn+j*8+gq,kc,bl); \
        mma_bf16(acc[0][j],ah0,bh); mma_bf16(acc[0][j],ah0,bl); mma_bf16(acc[0][j],al0,bh); \
        mma_bf16(acc[1][j],ah1,bh); mma_bf16(acc[1][j],ah1,bl); mma_bf16(acc[1][j],al1,bh); \
      } }

#define COMPUTE_KN() \
    for (int s=0;s<32;s+=16){ \
      const int kc=s+2*tq; \
      unsigned ah0[4],ah1[4],al0[4],al1[4]; \
      ldfragA(Ah,wm+gq,kc,ah0); ldfragA(Ah,wm+16+gq,kc,ah1); \
      ldfragA(Al,wm+gq,kc,al0); ldfragA(Al,wm+16+gq,kc,al1); \
      for(int j=0;j<8;j++){ \
        unsigned bh[2],bl[2]; \
        ldfragB_kn(Bh2,wn+j*8+gq,kc,bh); ldfragB_kn(Bl2,wn+j*8+gq,kc,bl); \
        mma_bf16(acc[0][j],ah0,bh); mma_bf16(acc[0][j],ah0,bl); mma_bf16(acc[0][j],al0,bh); \
        mma_bf16(acc[1][j],ah1,bh); mma_bf16(acc[1][j],ah1,bl); mma_bf16(acc[1][j],al1,bh); \
      } }

// K1: conv1x1 (256->512) + BN1 + ReLU
__global__ __launch_bounds__(256) void k1_conv1(
    const float* __restrict__ FT1, const float* __restrict__ FT2,
    const float* __restrict__ W,  const float* __restrict__ g1,
    const float* __restrict__ b1, const float* __restrict__ m1,
    const float* __restrict__ v1)
{
  __shared__ __nv_bfloat16 Ah[128][40], Al[128][40];
  __shared__ __nv_bfloat16 Bh2[32][136], Bl2[32][136];
  WDEF;
  const int b=blockIdx.z, m0=blockIdx.y*128, n0=blockIdx.x*128;
  const float* f1=FT1+(size_t)b*NCH*NPOS;
  const float* f2=FT2+(size_t)b*NCH*NPOS;
  float acc[2][8][4]={};
  for (int kt=0;kt<8;kt++){
    const int k0=kt*32;
    { const int lm=tid>>1, kb=(tid&1)*16;
      const float* sp=W+(size_t)(m0+lm)*INPC+k0+kb;
      for(int q=0;q<4;q++){ float4 v=*(const float4*)(sp+q*4); cvst(v,&Ah[lm][kb+q*4],&Al[lm][kb+q*4]); } }
    { const int kr=tid>>3, nb=(tid&7)*16;
      const int ci=k0+kr;
      const float* sp=((ci<NCH)?(f1+(size_t)ci*NPOS):(f2+(size_t)(ci-NCH)*NPOS))+n0+nb;
      for(int q=0;q<4;q++){ float4 v=*(const float4*)(sp+q*4); cvst(v,&Bh2[kr][nb+q*4],&Bl2[kr][nb+q*4]); } }
    __syncthreads();
    COMPUTE_KN();
    __syncthreads();
  }
  for(int i=0;i<2;i++) for(int hh=0;hh<2;hh++){
    const int r=m0+wm+i*16+gq+hh*8;
    const float sc=g1[r]*rsqrtf(v1[r]+EPSV);
    const float bi=b1[r]-m1[r]*sc;
    float* orow=g_x1+((size_t)b*ICC+r)*NPOS+n0;
    for(int j=0;j<8;j++){
      const int c0=wn+j*8+2*tq;
      float2 o;
      o.x=fmaxf(fmaf(acc[i][j][hh*2+0],sc,bi),0.f);
      o.y=fmaxf(fmaf(acc[i][j][hh*2+1],sc,bi),0.f);
      *(float2*)&orow[c0]=o;
    }
  }
}

// K2: depthwise 3x3 + BN2 + ReLU
__global__ __launch_bounds__(256) void k2_dw(
    const float* __restrict__ W3, const float* __restrict__ g2,
    const float* __restrict__ b2, const float* __restrict__ m2,
    const float* __restrict__ v2)
{
  const int bc=blockIdx.x, c=bc&(ICC-1);
  const float* plane=g_x1+(size_t)bc*NPOS;
  float w[9];
#pragma unroll
  for (int i=0;i<9;i++) w[i]=W3[c*9+i];
  const float sc=g2[c]*rsqrtf(v2[c]+EPSV);
  const float bi=b2[c]-m2[c]*sc;
  float* outp=g_x2+(size_t)bc*NPOS;
  for (int p=threadIdx.x;p<NPOS;p+=256){
    const int h=p>>6, ww=p&63;
    float a=0.f;
#pragma unroll
    for (int di=-1;di<=1;di++){
      const int hh=h+di;
      if ((unsigned)hh<64u){
#pragma unroll
        for (int dj=-1;dj<=1;dj++){
          const int wq=ww+dj;
          if ((unsigned)wq<64u) a=fmaf(w[(di+1)*3+dj+1],plane[hh*64+wq],a);
        }
      }
    }
    outp[p]=fmaxf(fmaf(a,sc,bi),0.f);
  }
}

// SE mean
__global__ __launch_bounds__(256) void k_se_reduce()
{
  __shared__ float red[256];
  const int bc=blockIdx.x, b=bc>>10, c=bc&1023;
  const float* plane=(c<ICC)?(g_x1+((size_t)b*ICC+c)*NPOS):(g_x2+((size_t)b*ICC+(c-ICC))*NPOS);
  float s=0.f;
  for (int p=threadIdx.x;p<NPOS;p+=256) s+=plane[p];
  red[threadIdx.x]=s; __syncthreads();
  for (int o=128;o>0;o>>=1){ if(threadIdx.x<o) red[threadIdx.x]+=red[threadIdx.x+o]; __syncthreads(); }
  if (threadIdx.x==0) g_s0[b*UPC+c]=red[0]*(1.f/NPOS);
}

// SE MLP: warp-per-hidden-row, coalesced
__global__ __launch_bounds__(256) void k_se_mlp(const float* __restrict__ w1, const float* __restrict__ w2)
{
  __shared__ float s0[1024];
  __shared__ float hid[64];
  const int b=blockIdx.x, tid=threadIdx.x, wd=tid>>5, ln=tid&31;
  for (int c=tid;c<1024;c+=256) s0[c]=g_s0[b*UPC+c];
  __syncthreads();
  for (int jj=0;jj<8;jj++){
    const int j=wd*8+jj;
    float p=0.f;
    for (int c=ln;c<1024;c+=32) p=fmaf(s0[c],w1[j*1024+c],p);
#pragma unroll
    for (int o=16;o>0;o>>=1) p+=__shfl_xor_sync(0xffffffffu,p,o);
    if (ln==0) hid[j]=fmaxf(p,0.f);
  }
  __syncthreads();
  const int c=blockIdx.y*256+tid;
  const float4* w2r=(const float4*)(w2+c*64);
  float a=0.f;
#pragma unroll
  for (int q=0;q<16;q++){
    float4 wv=w2r[q];
    a=fmaf(hid[q*4],wv.x,a); a=fmaf(hid[q*4+1],wv.y,a);
    a=fmaf(hid[q*4+2],wv.z,a); a=fmaf(hid[q*4+3],wv.w,a);
  }
  g_s[b*UPC+c]=sigf(a);
}

// K4: proj conv1x1 (1024->128) + SE scale + BN3
__global__ __launch_bounds__(256) void k4_proj(
    const float* __restrict__ PW, const float* __restrict__ g3,
    const float* __restrict__ b3, const float* __restrict__ m3,
    const float* __restrict__ v3)
{
  __shared__ __nv_bfloat16 Ah[128][40], Al[128][40];
  __shared__ __nv_bfloat16 Bh2[32][136], Bl2[32][136];
  WDEF;
  const int b=blockIdx.z, n0=blockIdx.x*128;
  float acc[2][8][4]={};
  for (int kt=0;kt<32;kt++){
    const int k0=kt*32;
    { const int lm=tid>>1, kb=(tid&1)*16;
      const float* sp=PW+(size_t)lm*UPC+k0+kb;
      for(int q=0;q<4;q++){ float4 v=*(const float4*)(sp+q*4); cvst(v,&Ah[lm][kb+q*4],&Al[lm][kb+q*4]); } }
    { const int kr=tid>>3, nb=(tid&7)*16;
      const int ci=k0+kr;
      const float* sp=((ci<ICC)?(g_x1+((size_t)b*ICC+ci)*NPOS):(g_x2+((size_t)b*ICC+(ci-ICC))*NPOS))+n0+nb;
      const float sv=g_s[b*UPC+ci];
      for(int q=0;q<4;q++){ float4 v=*(const float4*)(sp+q*4);
        v.x*=sv; v.y*=sv; v.z*=sv; v.w*=sv;
        cvst(v,&Bh2[kr][nb+q*4],&Bl2[kr][nb+q*4]); } }
    __syncthreads();
    COMPUTE_KN();
    __syncthreads();
  }
  for(int i=0;i<2;i++) for(int hh=0;hh<2;hh++){
    const int r=wm+i*16+gq+hh*8;
    const float sc=g3[r]*rsqrtf(v3[r]+EPSV);
    const float bi=b3[r]-m3[r]*sc;
    float* orow=g_Fp+((size_t)b*MDC+r)*NPOS+n0;
    for(int j=0;j<8;j++){
      const int c0=wn+j*8+2*tq;
      float2 o;
      o.x=fmaf(acc[i][j][hh*2+0],sc,bi);
      o.y=fmaf(acc[i][j][hh*2+1],sc,bi);
      *(float2*)&orow[c0]=o;
    }
  }
}

// K5: build X4 via SMEM-tiled transpose. grid (128, 32)
__global__ __launch_bounds__(256) void k5_x4()
{
  __shared__ float buf[128][33];
  const int tid=threadIdx.x;
  const int n=blockIdx.y, pbase=blockIdx.x*32;
  const int dir=n>>3, b=n&7;
  const float* fpb=g_Fp+(size_t)b*MDC*NPOS;
#pragma unroll
  for (int c=0;c<16;c++){
    const int idx=c*256+tid;
    const int d=idx>>5, pi=idx&31;
    buf[d][pi]=fpb[(size_t)d*NPOS+pbase+pi];
  }
  __syncthreads();
#pragma unroll
  for (int c=0;c<4;c++){
    const int idx=c*256+tid;
    const int pi=idx>>5, dq=(idx&31)*4;
    const int p=pbase+pi;
    int l;
    if (dir==0)      l=p;
    else if (dir==1) l=(p&~63)+63-(p&63);
    else if (dir==2) l=((p&63)<<6)+(p>>6);
    else             l=((p&63)<<6)+63-(p>>6);
    float4 v={buf[dq][pi],buf[dq+1][pi],buf[dq+2][pi],buf[dq+3][pi]};
    *(float4*)&g_X4[((size_t)n*LSEQ+l)*MDC+dq]=v;
  }
}

// K6: in_proj GEMM (131072x128 @ 512x128^T). grid (4,1024)
__global__ __launch_bounds__(256) void k6_inproj(const float* __restrict__ Wi)
{
  __shared__ __nv_bfloat16 Ah[128][40], Al[128][40];
  __shared__ __nv_bfloat16 Bh[128][40], Bl[128][40];
  WDEF;
  const int n0=blockIdx.x*128;
  const size_t m0=(size_t)blockIdx.y*128;
  float acc[2][8][4]={};
  for (int kt=0;kt<4;kt++){
    const int k0=kt*32;
    { const int lm=tid>>1, kb=(tid&1)*16;
      const float* sp=g_X4+(m0+lm)*MDC+k0+kb;
      for(int q=0;q<4;q++){ float4 v=*(const float4*)(sp+q*4); cvst(v,&Ah[lm][kb+q*4],&Al[lm][kb+q*4]); } }
    { const int lm=tid>>1, kb=(tid&1)*16;
      const float* sp=Wi+(size_t)(n0+lm)*MDC+k0+kb;
      for(int q=0;q<4;q++){ float4 v=*(const float4*)(sp+q*4); cvst(v,&Bh[lm][kb+q*4],&Bl[lm][kb+q*4]); } }
    __syncthreads();
    COMPUTE_NK();
    __syncthreads();
  }
  for(int i=0;i<2;i++) for(int hh=0;hh<2;hh++){
    const size_t r=m0+wm+i*16+gq+hh*8;
    float* orow=g_xz+r*(2*DINC)+n0;
    for(int j=0;j<8;j++){
      const int c0=wn+j*8+2*tq;
      float2 o={acc[i][j][hh*2+0],acc[i][j][hh*2+1]};
      *(float2*)&orow[c0]=o;
    }
  }
}

// K7: causal conv1d + SiLU
__global__ __launch_bounds__(256) void k7_conv1d(const float* __restrict__ CW, const float* __restrict__ CB)
{
  const int gid=blockIdx.x*256+threadIdx.x;
  const int d4=(gid&63)*4;
  const int l=(gid>>6)&4095;
  const int n=gid>>18;
  const float* base=g_xz+(size_t)n*LSEQ*(2*DINC)+d4;
  float4 acc={CB[d4],CB[d4+1],CB[d4+2],CB[d4+3]};
  float w[4][4];
#pragma unroll
  for (int i=0;i<4;i++){
    float4 wr=*(const float4*)&CW[(d4+i)*4];
    w[i][0]=wr.x; w[i][1]=wr.y; w[i][2]=wr.z; w[i][3]=wr.w;
  }
#pragma unroll
  for (int k=0;k<4;k++){
    const int lt=l-3+k;
    if (lt>=0){
      float4 x=*(const float4*)&base[(size_t)lt*(2*DINC)];
      acc.x=fmaf(w[0][k],x.x,acc.x); acc.y=fmaf(w[1][k],x.y,acc.y);
      acc.z=fmaf(w[2][k],x.z,acc.z); acc.w=fmaf(w[3][k],x.w,acc.w);
    }
  }
  acc.x*=sigf(acc.x); acc.y*=sigf(acc.y);
  acc.z*=sigf(acc.z); acc.w*=sigf(acc.w);
  *(float4*)&g_u[((size_t)n*LSEQ+l)*DINC+d4]=acc;
}

// K8: x_proj
__global__ __launch_bounds__(256) void k8_xproj(const float* __restrict__ XW)
{
  __shared__ float xw[10*DINC];
  const int tid=threadIdx.x;
  for (int i=tid;i<10*DINC;i+=256) xw[i]=XW[i];
  __syncthreads();
  const int warp=tid>>5, lane=tid&31;
  const size_t r=(size_t)blockIdx.x*8+warp;
  const float* urow=g_u+r*DINC;
  float uv[8];
#pragma unroll
  for (int i=0;i<8;i++) uv[i]=urow[lane+32*i];
#pragma unroll
  for (int j=0;j<10;j++){
    float p=0.f;
#pragma unroll
    for (int i=0;i<8;i++) p=fmaf(uv[i],xw[j*DINC+lane+32*i],p);
#pragma unroll
    for (int o=16;o>0;o>>=1) p+=__shfl_xor_sync(0xffffffffu,p,o);
    if (lane==0) g_dbl[r*10+j]=p;
  }
}

// K9: dt softplus
__global__ __launch_bounds__(256) void k9_dt(const float* __restrict__ DTW, const float* __restrict__ DTB)
{
  const int d=threadIdx.x;
  float w[8];
#pragma unroll
  for (int q=0;q<8;q++) w[q]=DTW[d*8+q];
  const float bb=DTB[d];
  const size_t r0=(size_t)blockIdx.x*8;
  for (int rr=0;rr<8;rr++){
    const size_t r=r0+rr;
    const float* db=g_dbl+r*10;
    float pre=bb;
#pragma unroll
    for (int q=0;q<8;q++) pre=fmaf(db[q],w[q],pre);
    const float sp=(pre>20.f)?pre:logf(1.f+__expf(pre));
    g_dt[r*DINC+d]=sp;
    if (d==0){ g_Bv[r]=db[8]; g_Cv[r]=db[9]; }
  }
}

// K10: selective scan
__global__ __launch_bounds__(256) void k10_scan(const float* __restrict__ AL, const float* __restrict__ DP)
{
  const int n=blockIdx.x, d=threadIdx.x;
  const float Ad=-__expf(AL[d]);
  const float Dpd=DP[d];
  const size_t base=(size_t)n*LSEQ;
  const float* up =g_u +base*DINC+d;
  const float* dtp=g_dt+base*DINC+d;
  const float* zp =g_xz+base*(2*DINC)+DINC+d;
  const float* bp =g_Bv+base;
  const float* cp =g_Cv+base;
  float* yp=g_yf+base*DINC+d;
  float h=0.f;
#pragma unroll 4
  for (int t=0;t<LSEQ;t++){
    const float uv =up [(size_t)t*DINC];
    const float dtv=dtp[(size_t)t*DINC];
    const float zv =zp [(size_t)t*(2*DINC)];
    const float bv =bp[t];
    const float cv =cp[t];
    const float a=__expf(dtv*Ad);
    h=fmaf(h,a,dtv*bv*uv);
    const float y=fmaf(h,cv,uv*Dpd);
    yp[(size_t)t*DINC]=y*zv*sigf(zv);
  }
}

// K11: out_proj GEMM. grid (1024)
__global__ __launch_bounds__(256) void k11_outproj(const float* __restrict__ OW)
{
  __shared__ __nv_bfloat16 Ah[128][40], Al[128][40];
  __shared__ __nv_bfloat16 Bh[128][40], Bl[128][40];
  WDEF;
  const size_t m0=(size_t)blockIdx.x*128;
  float acc[2][8][4]={};
  for (int kt=0;kt<8;kt++){
    const int k0=kt*32;
    { const int lm=tid>>1, kb=(tid&1)*16;
      const float* sp=g_yf+(m0+lm)*DINC+k0+kb;
      for(int q=0;q<4;q++){ float4 v=*(const float4*)(sp+q*4); cvst(v,&Ah[lm][kb+q*4],&Al[lm][kb+q*4]); } }
    { const int lm=tid>>1, kb=(tid&1)*16;
      const float* sp=OW+(size_t)lm*DINC+k0+kb;
      for(int q=0;q<4;q++){ float4 v=*(const float4*)(sp+q*4); cvst(v,&Bh[lm][kb+q*4],&Bl[lm][kb+q*4]); } }
    __syncthreads();
    COMPUTE_NK();
    __syncthreads();
  }
  for(int i=0;i<2;i++) for(int hh=0;hh<2;hh++){
    const size_t r=m0+wm+i*16+gq+hh*8;
    float* orow=g_Y4+r*MDC;
    for(int j=0;j<8;j++){
      const int c0=wn+j*8+2*tq;
      float2 o={acc[i][j][hh*2+0],acc[i][j][hh*2+1]};
      *(float2*)&orow[c0]=o;
    }
  }
}

// K12: pi gate GEMM (M-tile 64) + combine + 4-dir sum. grid (64,8)
__global__ __launch_bounds__(256) void k12_pi(const float* __restrict__ PW, const float* __restrict__ PB)
{
  __shared__ __nv_bfloat16 Ah[64][40], Al[64][40];
  __shared__ __nv_bfloat16 Bh[128][40], Bl[128][40];
  const int tid=threadIdx.x, wid=tid>>5, lane=tid&31, gq=lane>>2, tq=lane&3;
  const int wm=(wid>>1)*16, wn=(wid&1)*64;
  const int b=blockIdx.y, l0=blockIdx.x*64;
  float ys[8][4]={};
  for (int dir=0;dir<4;dir++){
    const size_t rowbase=((size_t)(dir*BQ+b))*LSEQ+l0;
    float acc[8][4]={};
    for (int kt=0;kt<8;kt++){
      const float* asrc=(kt<4)?g_X4:g_Y4;
      const int koff=(kt&3)*32;
      { const int lm=tid>>2, kb=(tid&3)*8;
        const float* sp=asrc+(rowbase+lm)*MDC+koff+kb;
        for(int q=0;q<2;q++){ float4 v=*(const float4*)(sp+q*4); cvst(v,&Ah[lm][kb+q*4],&Al[lm][kb+q*4]); } }
      { const int lm=tid>>1, kb=(tid&1)*16;
        const float* sp=PW+(size_t)lm*(2*MDC)+kt*32+kb;
        for(int q=0;q<4;q++){ float4 v=*(const float4*)(sp+q*4); cvst(v,&Bh[lm][kb+q*4],&Bl[lm][kb+q*4]); } }
      __syncthreads();
      for (int s=0;s<32;s+=16){
        const int kc=s+2*tq;
        unsigned ah[4],al[4];
        ldfragA(Ah,wm+gq,kc,ah);
        ldfragA(Al,wm+gq,kc,al);
        for(int j=0;j<8;j++){
          unsigned bh[2],bl[2];
          ldfragB_nk(Bh,wn+j*8+gq,kc,bh); ldfragB_nk(Bl,wn+j*8+gq,kc,bl);
          mma_bf16(acc[j],ah,bh); mma_bf16(acc[j],ah,bl); mma_bf16(acc[j],al,bh);
        }
      }
      __syncthreads();
    }
    for(int hh=0;hh<2;hh++){
      const size_t rg=rowbase+wm+gq+hh*8;
      for(int j=0;j<8;j++){
        const int c0=wn+j*8+2*tq;
        const float2 x2=*(const float2*)&g_X4[rg*MDC+c0];
        const float2 y2=*(const float2*)&g_Y4[rg*MDC+c0];
        const float p0=sigf(acc[j][hh*2+0]+PB[c0]);
        const float p1=sigf(acc[j][hh*2+1]+PB[c0+1]);
        ys[j][hh*2+0]+=x2.x+(y2.x-x2.x)*p0;
        ys[j][hh*2+1]+=x2.y+(y2.y-x2.y)*p1;
      }
    }
  }
  for(int hh=0;hh<2;hh++){
    const size_t r=(size_t)b*LSEQ+l0+wm+gq+hh*8;
    float* orow=g_ysum+r*MDC;
    for(int j=0;j<8;j++){
      const int c0=wn+j*8+2*tq;
      float2 o={ys[j][hh*2+0],ys[j][hh*2+1]};
      *(float2*)&orow[c0]=o;
    }
  }
}

// K13: final conv1x1 over (f_scan + Fp). grid (32,8)
__global__ __launch_bounds__(256) void k13_final(const float* __restrict__ FW, float* __restrict__ out)
{
  __shared__ __nv_bfloat16 Ah[128][40], Al[128][40];
  __shared__ __nv_bfloat16 Bh[128][40], Bl[128][40];
  WDEF;
  const int b=blockIdx.y, n0=blockIdx.x*128;
  const float* fpb=g_Fp+(size_t)b*MDC*NPOS;
  const float* ysb=g_ysum+(size_t)b*LSEQ*MDC;
  float acc[2][8][4]={};
  for (int kt=0;kt<4;kt++){
    const int k0=kt*32;
    { const int lm=tid>>1, kb=(tid&1)*16;
      const float* sp=FW+(size_t)lm*MDC+k0+kb;
      for(int q=0;q<4;q++){ float4 v=*(const float4*)(sp+q*4); cvst(v,&Ah[lm][kb+q*4],&Al[lm][kb+q*4]); } }
    { const int lm=tid>>1, kb=(tid&1)*16;
      const float* sp=ysb+(size_t)(n0+lm)*MDC+k0+kb;
      for(int q=0;q<4;q++){ float4 v=*(const float4*)(sp+q*4);
        v.x+=fpb[(size_t)(k0+kb+q*4+0)*NPOS+n0+lm];
        v.y+=fpb[(size_t)(k0+kb+q*4+1)*NPOS+n0+lm];
        v.z+=fpb[(size_t)(k0+kb+q*4+2)*NPOS+n0+lm];
        v.w+=fpb[(size_t)(k0+kb+q*4+3)*NPOS+n0+lm];
        cvst(v,&Bh[lm][kb+q*4],&Bl[lm][kb+q*4]); } }
    __syncthreads();
    COMPUTE_NK();
    __syncthreads();
  }
  for(int i=0;i<2;i++) for(int hh=0;hh<2;hh++){
    const int co=wm+i*16+gq+hh*8;
    float* orow=out+((size_t)b*NCH+co)*NPOS+n0;
    for(int j=0;j<8;j++){
      const int c0=wn+j*8+2*tq;
      float2 o={acc[i][j][hh*2+0],acc[i][j][hh*2+1]};
      *(float2*)&orow[c0]=o;
    }
  }
}

extern "C" void kernel_launch(void* const* d_in, const int* in_sizes, int n_in,
                              void* d_out, int out_size)
{
  const float* FT1=(const float*)d_in[0];
  const float* FT2=(const float*)d_in[1];
  const float* gpw=(const float*)d_in[2];
  const float* g1=(const float*)d_in[3];
  const float* b1=(const float*)d_in[4];
  const float* m1=(const float*)d_in[5];
  const float* v1=(const float*)d_in[6];
  const float* gcw=(const float*)d_in[7];
  const float* g2=(const float*)d_in[8];
  const float* b2=(const float*)d_in[9];
  const float* m2=(const float*)d_in[10];
  const float* v2=(const float*)d_in[11];
  const float* se1=(const float*)d_in[12];
  const float* se2=(const float*)d_in[13];
  const float* pjw=(const float*)d_in[14];
  const float* g3=(const float*)d_in[15];
  const float* b3=(const float*)d_in[16];
  const float* m3=(const float*)d_in[17];
  const float* v3=(const float*)d_in[18];
  const float* inw=(const float*)d_in[19];
  const float* c1w=(const float*)d_in[20];
  const float* c1b=(const float*)d_in[21];
  const float* xpw=(const float*)d_in[22];
  const float* dtw=(const float*)d_in[23];
  const float* dtb=(const float*)d_in[24];
  const float* alog=(const float*)d_in[25];
  const float* dp=(const float*)d_in[26];
  const float* opw=(const float*)d_in[27];
  const float* piw=(const float*)d_in[28];
  const float* pib=(const float*)d_in[29];
  const float* fw=(const float*)d_in[30];
  float* out=(float*)d_out;

  k1_conv1   <<<dim3(32,4,8),256>>>(FT1,FT2,gpw,g1,b1,m1,v1);
  k2_dw      <<<BQ*ICC,256>>>(gcw,g2,b2,m2,v2);
  k_se_reduce<<<BQ*UPC,256>>>();
  k_se_mlp   <<<dim3(8,4),256>>>(se1,se2);
  k4_proj    <<<dim3(32,1,8),256>>>(pjw,g3,b3,m3,v3);
  k5_x4      <<<dim3(128,32),256>>>();
  k6_inproj  <<<dim3(4,1024),256>>>(inw);
  k7_conv1d  <<<(NSEQ*LSEQ*DINC/4)/256,256>>>(c1w,c1b);
  k8_xproj   <<<NSEQ*LSEQ/8,256>>>(xpw);
  k9_dt      <<<NSEQ*LSEQ/8,256>>>(dtw,dtb);
  k10_scan   <<<NSEQ,256>>>(alog,dp);
  k11_outproj<<<NSEQ*LSEQ/128,256>>>(opw);
  k12_pi     <<<dim3(64,8),256>>>(piw,pib);
  k13_final  <<<dim3(32,8),256>>>(fw,out);
}